// round 17
// baseline (speedup 1.0000x reference)
#include <cuda_runtime.h>
#include <cuda_fp16.h>
#include <cstdint>
#include <math.h>

#define B_   8192
#define T_   10
#define F_   561
#define H_   256
#define O_   12
#define NBT  (B_ * T_)          // 81920
#define KXS  576                // 561 padded to 9*64
#define AXPW 256                // xp stored as single fp16 segment
#define K4H  1024               // Act row: [h0hi|h0lo|h1hi|h1lo]
#define KW   768                // recurrent weight row: [W_in | W_hh | W_hh]
#define G4H  1024
#define NJOBS 20
#define ROWBLKS 64
#define NXP   1280              // xp tiles: 640 rowblocks x 2 colblocks
#define NREC  (NJOBS * 512)     // 10240
#define NPROJ 640               // proj tiles: 128 NBT-rows each
#define NGRID (NXP + NREC + NPROJ)

#define SWZ128(off) ((off) ^ (((off) >> 3) & 0x70))

__device__ __forceinline__ uint32_t smem_u32(const void* p) {
    uint32_t a;
    asm("{ .reg .u64 t; cvta.to.shared.u64 t, %1; cvt.u32.u64 %0, t; }" : "=r"(a) : "l"(p));
    return a;
}
__device__ __forceinline__ void ldsm_x4(uint32_t* r, uint32_t addr) {
    asm volatile("ldmatrix.sync.aligned.m8n8.x4.shared.b16 {%0,%1,%2,%3}, [%4];"
                 : "=r"(r[0]), "=r"(r[1]), "=r"(r[2]), "=r"(r[3]) : "r"(addr));
}
__device__ __forceinline__ void mma_f16(float* d, const uint32_t* a, uint32_t b0, uint32_t b1) {
    asm volatile("mma.sync.aligned.m16n8k16.row.col.f32.f16.f16.f32 "
                 "{%0,%1,%2,%3}, {%4,%5,%6,%7}, {%8,%9}, {%0,%1,%2,%3};"
                 : "+f"(d[0]), "+f"(d[1]), "+f"(d[2]), "+f"(d[3])
                 : "r"(a[0]), "r"(a[1]), "r"(a[2]), "r"(a[3]), "r"(b0), "r"(b1));
}

#define LOG2E 1.4426950408889634f
__device__ __forceinline__ float fexp2(float x){ float r; asm("ex2.approx.f32 %0, %1;" : "=f"(r) : "f"(x)); return r; }
__device__ __forceinline__ float frcpa(float x){ float r; asm("rcp.approx.f32 %0, %1;" : "=f"(r) : "f"(x)); return r; }
__device__ __forceinline__ float fsig(float x){ return frcpa(1.f + fexp2(-LOG2E * x)); }
__device__ __forceinline__ float ftanh_(float x){
    float xc = fminf(fmaxf(x, -20.f), 20.f);
    float e = fexp2(2.f * LOG2E * xc);
    return (e - 1.f) * frcpa(e + 1.f);
}
__device__ __forceinline__ void split_f16(float x, __half& hi, __half& lo) {
    hi = __float2half_rn(x);
    lo = __float2half_rn(x - __half2float(hi));
}

// ======================= scratch =======================
__device__ __half g_Xh[(size_t)NBT * KXS];
__device__ __half g_Axp[(size_t)NBT * AXPW];
__device__ __half g_Act[(size_t)(T_ + 1) * B_ * K4H];   // per-step h buffers; Act[0] = zeros
__device__ float  g_c0[B_ * H_];
__device__ float  g_c1[B_ * H_];
__device__ float  g_hs[(size_t)NBT * H_];
__device__ __half g_WbInp[(size_t)H_ * KXS];
__device__ __half g_Wc0[(size_t)G4H * KW];
__device__ __half g_Wc1[(size_t)G4H * KW];
__device__ float  g_bias0[G4H];
__device__ float  g_bias1[G4H];
__device__ int    g_flags[NJOBS * ROWBLKS];
__device__ int    g_xflags[NBT / 128];                  // 640, each counts to 2

// ======================= tile config =======================
#define TM_ 128
#define TN_ 128
#define KC  64
#define SM_A0  0
#define SM_A1  16384
#define SM_B0  32768
#define SM_B1  49152
#define SM_TOTAL 65536
#define STAGE_LD 72
#define NCH2 12

// ======================= prep (everything in one kernel) =======================
__global__ void prep_all(const float* __restrict__ X, const float* __restrict__ W_inp,
                         const float* __restrict__ Wih0, const float* __restrict__ Whh0,
                         const float* __restrict__ bih0, const float* __restrict__ bhh0,
                         const float* __restrict__ Wih1, const float* __restrict__ Whh1,
                         const float* __restrict__ bih1, const float* __restrict__ bhh1)
{
    const long stride = (long)gridDim.x * blockDim.x;
    const long tid0 = blockIdx.x * (long)blockDim.x + threadIdx.x;

    // zero Act[0], c, flags, WbInp pad
    for (long i = tid0; i < (long)B_ * K4H; i += stride) g_Act[i] = __float2half(0.f);
    for (long i = tid0; i < B_ * H_; i += stride) { g_c0[i] = 0.f; g_c1[i] = 0.f; }
    for (long i = tid0; i < NJOBS * ROWBLKS; i += stride) g_flags[i] = 0;
    for (long i = tid0; i < NBT / 128; i += stride) g_xflags[i] = 0;
    for (long i = tid0; i < H_ * (KXS - F_); i += stride) {
        long r = i / (KXS - F_), c = i % (KXS - F_);
        g_WbInp[r * KXS + F_ + c] = __float2half(0.f);
    }
    // X -> fp16 padded
    for (long i = tid0; i < (long)NBT * KXS; i += stride) {
        long row = i / KXS; int col = (int)(i % KXS);
        g_Xh[i] = (col < F_) ? __float2half_rn(X[row * F_ + col]) : __float2half(0.f);
    }
    // W_inp pack
    for (long i = tid0; i < (long)H_ * F_; i += stride) {
        long r = i / F_, k = i % F_;
        g_WbInp[r * KXS + k] = __float2half_rn(W_inp[i]);
    }
    // gate-interleaved recurrent weights (n = j*4+g), rows [W_in | W_hh | W_hh]
    for (long i = tid0; i < (long)G4H * H_; i += stride) {
        int n = (int)(i >> 8), k = (int)(i & 255);
        int j = n >> 2, g = n & 3;
        int r = g * 256 + j;
        {
            __half* row = g_Wc0 + (size_t)n * KW;
            row[k]       = __float2half_rn(Wih0[r * 256 + k]);
            __half wh    = __float2half_rn(Whh0[r * 256 + k]);
            row[256 + k] = wh; row[512 + k] = wh;
            if (k == 0) g_bias0[n] = bih0[r] + bhh0[r];
        }
        {
            __half* row = g_Wc1 + (size_t)n * KW;
            row[k]       = __float2half_rn(Wih1[r * 256 + k]);
            __half wh    = __float2half_rn(Whh1[r * 256 + k]);
            row[256 + k] = wh; row[512 + k] = wh;
            if (k == 0) g_bias1[n] = bih1[r] + bhh1[r];
        }
    }
}

// ======================= mega persistent kernel =======================
// bids [0, NXP):            xp tiles — Axp = fp16(Xh @ WbInp^T + b_inp)
// bids [NXP, NXP+NREC):     recurrence (20 jobs x 512 tiles, flag-synced)
// bids [NXP+NREC, NGRID):   output projection (reads g_hs, waits on layer1 flags)
__global__ void __launch_bounds__(256)
mega(const float* __restrict__ b_inp,
     const float* __restrict__ W_out, const float* __restrict__ b_out,
     float* __restrict__ out, float* __restrict__ hn_base, float* __restrict__ cn_base)
{
    extern __shared__ char smem[];
    const uint32_t sb = smem_u32(smem);
    const int tid  = threadIdx.x;
    const int wid  = tid >> 5;
    const int lane = tid & 31;
    const int wm   = wid >> 1;
    const int wn   = wid & 1;
    const uint32_t abuf[2] = { sb + SM_A0, sb + SM_A1 };
    const uint32_t bbuf[2] = { sb + SM_B0, sb + SM_B1 };
    const int bid = blockIdx.x;

    // =====================================================================
    if (bid < NXP) {
        // ---------------- xp GEMM tile ----------------
        const int rowblk = bid >> 1;
        const int colblk = bid & 1;
        const long rowBase = (long)rowblk * TM_;
        const long colBase = (long)colblk * TN_;
        const __half* A  = g_Xh;
        const __half* Bw = g_WbInp;

        float acc[2][8][4];
#pragma unroll
        for (int i = 0; i < 2; i++)
#pragma unroll
            for (int j = 0; j < 8; j++)
#pragma unroll
                for (int k = 0; k < 4; k++) acc[i][j][k] = 0.f;

        const int nch = KXS / KC;   // 9

#define XLOAD(c, buf) do { \
    _Pragma("unroll") \
    for (int l = 0; l < 4; l++) { \
        int idx = tid + 256 * l; int r = idx >> 3, v = idx & 7; \
        const void* gp = A + (rowBase + r) * (long)KXS + (long)(c) * KC + v * 8; \
        uint32_t s = abuf[buf] + SWZ128(r * 128 + v * 16); \
        asm volatile("cp.async.cg.shared.global [%0], [%1], 16;\n" :: "r"(s), "l"(gp)); \
    } \
    _Pragma("unroll") \
    for (int l = 0; l < 4; l++) { \
        int idx = tid + 256 * l; int r = idx >> 3, v = idx & 7; \
        const void* gp = Bw + (colBase + r) * (long)KXS + (long)(c) * KC + v * 8; \
        uint32_t s = bbuf[buf] + SWZ128(r * 128 + v * 16); \
        asm volatile("cp.async.cg.shared.global [%0], [%1], 16;\n" :: "r"(s), "l"(gp)); \
    } \
    asm volatile("cp.async.commit_group;\n"); \
} while (0)

        XLOAD(0, 0);
        XLOAD(1, 1);
        for (int c = 0; c < nch; c++) {
            const int buf = c & 1;
            if (c + 1 < nch) asm volatile("cp.async.wait_group 1;\n" ::: "memory");
            else             asm volatile("cp.async.wait_group 0;\n" ::: "memory");
            __syncthreads();
            const uint32_t As = abuf[buf], Bs = bbuf[buf];
#pragma unroll
            for (int ks = 0; ks < 4; ks++) {
                uint32_t afr[2][4];
#pragma unroll
                for (int mt = 0; mt < 2; mt++) {
                    int row = wm * 32 + mt * 16 + (lane & 15);
                    int kc  = ks * 16 + ((lane >> 4) << 3);
                    ldsm_x4(afr[mt], As + SWZ128(row * 128 + kc * 2));
                }
                uint32_t bfr[4][4];
#pragma unroll
                for (int bt = 0; bt < 4; bt++) {
                    int nr = wn * 64 + bt * 16 + (lane & 7) + ((lane >> 4) << 3);
                    int kc = ks * 16 + (((lane >> 3) & 1) << 3);
                    ldsm_x4(bfr[bt], Bs + SWZ128(nr * 128 + kc * 2));
                }
#pragma unroll
                for (int mt = 0; mt < 2; mt++)
#pragma unroll
                    for (int nt = 0; nt < 8; nt++) {
                        const uint32_t* bp = bfr[nt >> 1];
                        if (nt & 1) mma_f16(acc[mt][nt], afr[mt], bp[2], bp[3]);
                        else        mma_f16(acc[mt][nt], afr[mt], bp[0], bp[1]);
                    }
            }
            __syncthreads();
            if (c + 2 < nch) XLOAD(c + 2, buf);
        }

#pragma unroll
        for (int mt = 0; mt < 2; mt++)
#pragma unroll
            for (int nt = 0; nt < 8; nt++) {
                long row = rowBase + wm * 32 + mt * 16 + (lane >> 2);
                long col = colBase + wn * 64 + nt * 8 + ((lane & 3) << 1);
                float2 bv = *(const float2*)&b_inp[col];
#pragma unroll
                for (int h = 0; h < 2; h++) {
                    long r2 = row + 8 * h;
                    float vx = acc[mt][nt][2 * h + 0] + bv.x;
                    float vy = acc[mt][nt][2 * h + 1] + bv.y;
                    *(__half2*)&g_Axp[r2 * AXPW + col] =
                        __halves2half2(__float2half_rn(vx), __float2half_rn(vy));
                }
            }
        __threadfence();
        __syncthreads();
        if (tid == 0) atomicAdd(&g_xflags[rowblk], 1);
        return;
    }

    // =====================================================================
    if (bid < NXP + NREC) {
        // ---------------- recurrence tile ----------------
        const int rb     = bid - NXP;
        const int job    = rb >> 9;
        const int within = rb & 511;
        const int rowblk = within >> 3;
        const int bx     = within & 7;
        const int t      = job >> 1;
        const int lay    = job & 1;

        __half* ActT  = g_Act + (size_t)t * B_ * K4H;
        __half* ActT1 = g_Act + (size_t)(t + 1) * B_ * K4H;

        const __half* A1; long lda1;
        const __half* A2;
        const __half* Wc;
        const float* biasF;
        float* cst;
        __half* Wact; int actOff;
        float* hsp; float* hnp; float* cnp;
        int depA, depB;

        if (lay == 0) {
            A1 = g_Axp + (size_t)t * AXPW; lda1 = (long)T_ * AXPW;
            A2 = ActT;
            Wc = g_Wc0; biasF = g_bias0; cst = g_c0;
            Wact = ActT1; actOff = 0;
            hsp = nullptr;
            hnp = (t == T_ - 1) ? hn_base : nullptr;
            cnp = (t == T_ - 1) ? cn_base : nullptr;
            depA = (t > 0) ? (job - 2) : -1;
            depB = -1;
        } else {
            A1 = ActT1; lda1 = (long)K4H;
            A2 = ActT + 512;
            Wc = g_Wc1; biasF = g_bias1; cst = g_c1;
            Wact = ActT1; actOff = 512;
            hsp = g_hs;
            hnp = (t == T_ - 1) ? (hn_base + (size_t)B_ * H_) : nullptr;
            cnp = (t == T_ - 1) ? (cn_base + (size_t)B_ * H_) : nullptr;
            depA = job - 1;
            depB = (t > 0) ? (job - 3) : -1;
        }

        const long rowBase = (long)rowblk * TM_;
        const long colBase = (long)bx * TN_;

        // wait: producers of this row-block (+ xp group for layer0)
        if (tid == 0) {
            volatile int* fl = (volatile int*)g_flags;
            if (lay == 0) {
                volatile int* xf = (volatile int*)g_xflags;
#pragma unroll
                for (int i = 0; i < 10; i++)
                    while (xf[rowblk * 10 + i] < 2) __nanosleep(64);
            }
            if (depA >= 0) while (fl[depA * ROWBLKS + rowblk] < 8) __nanosleep(64);
            if (depB >= 0) while (fl[depB * ROWBLKS + rowblk] < 8) __nanosleep(64);
            __threadfence();
        }
        __syncthreads();

        float acc[2][8][4];
#pragma unroll
        for (int i = 0; i < 2; i++)
#pragma unroll
            for (int j = 0; j < 8; j++)
#pragma unroll
                for (int k = 0; k < 4; k++) acc[i][j][k] = 0.f;

#define RLOAD(c, buf) do { \
    const __half* Asrc; long Alda; int cl; \
    if ((c) < 4) { Asrc = A1; Alda = lda1; cl = (c); } \
    else         { Asrc = A2; Alda = K4H;  cl = (c) - 4; } \
    _Pragma("unroll") \
    for (int l = 0; l < 4; l++) { \
        int idx = tid + 256 * l; int r = idx >> 3, v = idx & 7; \
        const void* gp = Asrc + (rowBase + r) * Alda + (long)cl * KC + v * 8; \
        uint32_t s = abuf[buf] + SWZ128(r * 128 + v * 16); \
        asm volatile("cp.async.cg.shared.global [%0], [%1], 16;\n" :: "r"(s), "l"(gp)); \
    } \
    _Pragma("unroll") \
    for (int l = 0; l < 4; l++) { \
        int idx = tid + 256 * l; int r = idx >> 3, v = idx & 7; \
        const void* gp = Wc + (colBase + r) * (long)KW + (long)(c) * KC + v * 8; \
        uint32_t s = bbuf[buf] + SWZ128(r * 128 + v * 16); \
        asm volatile("cp.async.cg.shared.global [%0], [%1], 16;\n" :: "r"(s), "l"(gp)); \
    } \
    asm volatile("cp.async.commit_group;\n"); \
} while (0)

        RLOAD(0, 0);
        RLOAD(1, 1);
        for (int c = 0; c < NCH2; c++) {
            const int buf = c & 1;
            if (c + 1 < NCH2) asm volatile("cp.async.wait_group 1;\n" ::: "memory");
            else              asm volatile("cp.async.wait_group 0;\n" ::: "memory");
            __syncthreads();
            const uint32_t As = abuf[buf], Bs = bbuf[buf];
#pragma unroll
            for (int ks = 0; ks < 4; ks++) {
                uint32_t afr[2][4];
#pragma unroll
                for (int mt = 0; mt < 2; mt++) {
                    int row = wm * 32 + mt * 16 + (lane & 15);
                    int kc  = ks * 16 + ((lane >> 4) << 3);
                    ldsm_x4(afr[mt], As + SWZ128(row * 128 + kc * 2));
                }
                uint32_t bfr[4][4];
#pragma unroll
                for (int bt = 0; bt < 4; bt++) {
                    int nr = wn * 64 + bt * 16 + (lane & 7) + ((lane >> 4) << 3);
                    int kc = ks * 16 + (((lane >> 3) & 1) << 3);
                    ldsm_x4(bfr[bt], Bs + SWZ128(nr * 128 + kc * 2));
                }
#pragma unroll
                for (int mt = 0; mt < 2; mt++)
#pragma unroll
                    for (int nt = 0; nt < 8; nt++) {
                        const uint32_t* bp = bfr[nt >> 1];
                        if (nt & 1) mma_f16(acc[mt][nt], afr[mt], bp[2], bp[3]);
                        else        mma_f16(acc[mt][nt], afr[mt], bp[0], bp[1]);
                    }
            }
            __syncthreads();
            if (c + 2 < NCH2) RLOAD(c + 2, buf);
        }

        // staged fused LSTM epilogue
        __syncthreads();
        float* stage = (float*)smem;
#pragma unroll 1
        for (int half = 0; half < 2; half++) {
            if (wn == half) {
#pragma unroll
                for (int mt = 0; mt < 2; mt++)
#pragma unroll
                    for (int nt = 0; nt < 8; nt++) {
                        int row_l = wm * 32 + mt * 16 + (lane >> 2);
                        int col_l = nt * 8 + ((lane & 3) << 1);
                        *(float2*)&stage[row_l * STAGE_LD + col_l] =
                            make_float2(acc[mt][nt][0], acc[mt][nt][1]);
                        *(float2*)&stage[(row_l + 8) * STAGE_LD + col_l] =
                            make_float2(acc[mt][nt][2], acc[mt][nt][3]);
                    }
            }
            __syncthreads();

            const int u_l = tid & 15;
            const long u_g = (long)bx * 32 + half * 16 + u_l;
            const float4 bv = *(const float4*)&biasF[u_g * 4];
#pragma unroll
            for (int rr = 0; rr < 8; rr++) {
                int row_l = (tid >> 4) + rr * 16;
                long b = rowBase + row_l;
                float4 gv = *(float4*)&stage[row_l * STAGE_LD + u_l * 4];
                float gi = gv.x + bv.x;
                float gf = gv.y + bv.y;
                float gg = gv.z + bv.z;
                float go = gv.w + bv.w;
                long cidx = b * H_ + u_g;
                float c_new = fsig(gf) * cst[cidx] + fsig(gi) * ftanh_(gg);
                float h_new = fsig(go) * ftanh_(c_new);
                cst[cidx] = c_new;
                __half hi, lo; split_f16(h_new, hi, lo);
                __half* a = Wact + b * K4H + actOff;
                a[u_g] = hi; a[u_g + 256] = lo;
                if (hsp) hsp[(b * T_ + t) * H_ + u_g] = h_new;
                if (hnp) { hnp[cidx] = h_new; cnp[cidx] = c_new; }
            }
            __syncthreads();
        }

        __threadfence();
        __syncthreads();
        if (tid == 0) atomicAdd(&g_flags[job * ROWBLKS + rowblk], 1);
        return;
    }

    // =====================================================================
    // ---------------- output projection tile ----------------
    {
        const int p = bid - (NXP + NREC);      // covers NBT rows [p*128, (p+1)*128)
        const int brb = p / 10;                // owning b-rowblock

        if (tid == 0) {
            volatile int* fl = (volatile int*)g_flags;
#pragma unroll
            for (int tt = 0; tt < T_; tt++)
                while (fl[(2 * tt + 1) * ROWBLKS + brb] < 8) __nanosleep(128);
            __threadfence();
        }
        __syncthreads();

        float* Ws = (float*)smem;              // 12*256 floats = 12 KB
        float* bs = Ws + O_ * H_;
        for (int i = tid; i < O_ * H_; i += 256) Ws[i] = W_out[i];
        if (tid < O_) bs[tid] = b_out[tid];
        __syncthreads();

        const int warp = wid;
#pragma unroll 1
        for (int it = 0; it < 16; it++) {
            long row = (long)p * 128 + it * 8 + warp;
            float x[H_ / 32];
#pragma unroll
            for (int j = 0; j < H_ / 32; j++) x[j] = g_hs[row * H_ + lane + 32 * j];
#pragma unroll
            for (int o = 0; o < O_; o++) {
                float s = 0.f;
#pragma unroll
                for (int j = 0; j < H_ / 32; j++) s = fmaf(x[j], Ws[o * H_ + lane + 32 * j], s);
#pragma unroll
                for (int off = 16; off > 0; off >>= 1) s += __shfl_xor_sync(0xffffffffu, s, off);
                if (lane == 0) out[row * O_ + o] = s + bs[o];
            }
        }
    }
}

// ======================= launch =======================
extern "C" void kernel_launch(void* const* d_in, const int* in_sizes, int n_in,
                              void* d_out, int out_size)
{
    (void)in_sizes; (void)n_in; (void)out_size;
    const float* X     = (const float*)d_in[0];
    const float* W_inp = (const float*)d_in[1];
    const float* b_inp = (const float*)d_in[2];
    const float* Wih0  = (const float*)d_in[3];
    const float* Whh0  = (const float*)d_in[4];
    const float* bih0  = (const float*)d_in[5];
    const float* bhh0  = (const float*)d_in[6];
    const float* Wih1  = (const float*)d_in[7];
    const float* Whh1  = (const float*)d_in[8];
    const float* bih1  = (const float*)d_in[9];
    const float* bhh1  = (const float*)d_in[10];
    const float* W_out = (const float*)d_in[11];
    const float* b_out = (const float*)d_in[12];

    float* out     = (float*)d_out;
    float* hn_base = out + (size_t)B_ * T_ * O_;
    float* cn_base = hn_base + (size_t)2 * B_ * H_;

    static bool init = false;
    if (!init) {
        cudaFuncSetAttribute(mega, cudaFuncAttributeMaxDynamicSharedMemorySize, SM_TOTAL);
        init = true;
    }

    prep_all<<<2048, 256>>>(X, W_inp, Wih0, Whh0, bih0, bhh0, Wih1, Whh1, bih1, bhh1);
    mega<<<NGRID, 256, SM_TOTAL>>>(b_inp, W_out, b_out, out, hn_base, cn_base);
}